// round 13
// baseline (speedup 1.0000x reference)
#include <cuda_runtime.h>
#include <cuda_bf16.h>
#include <cstdint>

// Problem constants
#define NB 8
#define NT 2048
#define NC 1024
#define NH 256

// Scratch (device globals)
__device__ __nv_bfloat16 g_qhi[NB*NT*NH], g_qlo[NB*NT*NH];
__device__ __nv_bfloat16 g_khi[NB*NT*NH], g_klo[NB*NT*NH];
__device__ __nv_bfloat16 g_vhi[NB*NT*NH], g_vlo[NB*NT*NH];
__device__ __nv_bfloat16 g_xhi[NB*NT*NC], g_xlo[NB*NT*NC];
__device__ __nv_bfloat16 g_whi[3*NC*NH],  g_wlo[3*NC*NH];

__device__ __forceinline__ uint32_t smem_u32(const void* p) {
    uint32_t a;
    asm("{ .reg .u64 t; cvta.to.shared.u64 t, %1; cvt.u32.u64 %0, t; }"
        : "=r"(a) : "l"(p));
    return a;
}
__device__ __forceinline__ void ldmx4(uint32_t* r, uint32_t addr) {
    asm volatile("ldmatrix.sync.aligned.m8n8.x4.shared.b16 {%0,%1,%2,%3}, [%4];"
        : "=r"(r[0]), "=r"(r[1]), "=r"(r[2]), "=r"(r[3]) : "r"(addr));
}
__device__ __forceinline__ void ldmx2(uint32_t* r, uint32_t addr) {
    asm volatile("ldmatrix.sync.aligned.m8n8.x2.shared.b16 {%0,%1}, [%2];"
        : "=r"(r[0]), "=r"(r[1]) : "r"(addr));
}
__device__ __forceinline__ void ldmx4t(uint32_t* r, uint32_t addr) {
    asm volatile("ldmatrix.sync.aligned.m8n8.x4.trans.shared.b16 {%0,%1,%2,%3}, [%4];"
        : "=r"(r[0]), "=r"(r[1]), "=r"(r[2]), "=r"(r[3]) : "r"(addr));
}
__device__ __forceinline__ void mma_bf16(float* c, const uint32_t* a, const uint32_t* b) {
    asm volatile("mma.sync.aligned.m16n8k16.row.col.f32.bf16.bf16.f32 "
        "{%0,%1,%2,%3}, {%4,%5,%6,%7}, {%8,%9}, {%0,%1,%2,%3};"
        : "+f"(c[0]), "+f"(c[1]), "+f"(c[2]), "+f"(c[3])
        : "r"(a[0]), "r"(a[1]), "r"(a[2]), "r"(a[3]), "r"(b[0]), "r"(b[1]));
}
__device__ __forceinline__ void cpa16(uint32_t dst, const void* src) {
    asm volatile("cp.async.cg.shared.global [%0], [%1], 16;" :: "r"(dst), "l"(src));
}
#define CP_COMMIT() asm volatile("cp.async.commit_group;" ::: "memory")
#define CP_WAIT1()  asm volatile("cp.async.wait_group 1;" ::: "memory")
#define CP_WAIT0()  asm volatile("cp.async.wait_group 0;" ::: "memory")

__device__ __forceinline__ uint32_t packbb(__nv_bfloat16 a, __nv_bfloat16 b) {
    unsigned short ua = *reinterpret_cast<unsigned short*>(&a);
    unsigned short ub = *reinterpret_cast<unsigned short*>(&b);
    return (uint32_t)ua | ((uint32_t)ub << 16);
}
__device__ __forceinline__ void split2(float v0, float v1, uint32_t& hw, uint32_t& lw) {
    __nv_bfloat16 h0 = __float2bfloat16(v0);
    __nv_bfloat16 h1 = __float2bfloat16(v1);
    __nv_bfloat16 l0 = __float2bfloat16(v0 - __bfloat162float(h0));
    __nv_bfloat16 l1 = __float2bfloat16(v1 - __bfloat162float(h1));
    hw = packbb(h0, h1);
    lw = packbb(l0, l1);
}

// ---------------------------------------------------------------------------
// Prep kernels: fp32 -> split bf16 hi/lo
// ---------------------------------------------------------------------------
__global__ void __launch_bounds__(256)
convert_x_kernel(const float* __restrict__ x)
{
    int idx = blockIdx.x * 256 + threadIdx.x;
    float4 v = ((const float4*)x)[idx];
    uint32_t h01, l01, h23, l23;
    split2(v.x, v.y, h01, l01);
    split2(v.z, v.w, h23, l23);
    ((uint2*)g_xhi)[idx] = make_uint2(h01, h23);
    ((uint2*)g_xlo)[idx] = make_uint2(l01, l23);
}

__global__ void __launch_bounds__(256)
convert_w_kernel(const float* __restrict__ Wq, const float* __restrict__ Wk,
                 const float* __restrict__ Wv)
{
    int idx = blockIdx.x * 256 + threadIdx.x;
    int z = idx >> 16;
    int j = idx & 65535;
    const float* W = (z == 0) ? Wq : ((z == 1) ? Wk : Wv);
    float s = (z == 0) ? 16.0f : 1.0f;           // fold sqrt(H) into Wq
    float4 v = ((const float4*)W)[j];
    uint32_t h01, l01, h23, l23;
    split2(v.x * s, v.y * s, h01, l01);
    split2(v.z * s, v.w * s, h23, l23);
    ((uint2*)g_whi)[idx] = make_uint2(h01, h23);
    ((uint2*)g_wlo)[idx] = make_uint2(l01, l23);
}

// ---------------------------------------------------------------------------
// Kernel 1: QKV projection GEMM (unchanged from R10 — measured good)
// ---------------------------------------------------------------------------
#define ASTR 40
#define WSTR 136
#define G_AH  0
#define G_AL  10240
#define G_WH  20480
#define G_WL  29184
#define G_BUF 37888
#define GEMM_SMEM (2 * G_BUF)

__device__ __forceinline__ void gemm_issue(uint32_t sbuf, const __nv_bfloat16* xh,
                                           const __nv_bfloat16* xl,
                                           const __nv_bfloat16* wh,
                                           const __nv_bfloat16* wl,
                                           int m0, int n0, int k0, int t)
{
    #pragma unroll
    for (int i = 0; i < 2; i++) {
        int idx = t + 256 * i;
        {
            int row = idx >> 2, seg = idx & 3;
            uint32_t d = sbuf + G_AH + row * (ASTR * 2) + seg * 16;
            size_t   g = (size_t)(m0 + row) * NC + k0 + seg * 8;
            cpa16(d, xh + g);
            cpa16(d + (G_AL - G_AH), xl + g);
        }
        {
            int row = idx >> 4, seg = idx & 15;
            uint32_t d = sbuf + G_WH + row * (WSTR * 2) + seg * 16;
            size_t   g = (size_t)(k0 + row) * NH + n0 + seg * 8;
            cpa16(d, wh + g);
            cpa16(d + (G_WL - G_WH), wl + g);
        }
    }
}

__global__ void __launch_bounds__(256, 2)
qkv_gemm_kernel()
{
    extern __shared__ char smg[];
    const uint32_t sb = smem_u32(smg);

    const int z = blockIdx.z;
    const __nv_bfloat16* wh = g_whi + (size_t)z * NC * NH;
    const __nv_bfloat16* wl = g_wlo + (size_t)z * NC * NH;
    __nv_bfloat16* ohi = (z == 0) ? g_qhi : ((z == 1) ? g_khi : g_vhi);
    __nv_bfloat16* olo = (z == 0) ? g_qlo : ((z == 1) ? g_klo : g_vlo);

    const int m0 = blockIdx.y * 128;
    const int n0 = blockIdx.x * 128;
    const int t  = threadIdx.x;
    const int l  = t & 31;
    const int wid = t >> 5;
    const int wm = wid & 1;
    const int wn = wid >> 1;
    const int lg = l >> 2;
    const int lt = l & 3;

    float acc[4][4][4];
    #pragma unroll
    for (int i = 0; i < 4; i++)
        #pragma unroll
        for (int j = 0; j < 4; j++)
            #pragma unroll
            for (int k = 0; k < 4; k++) acc[i][j][k] = 0.f;

    gemm_issue(sb, g_xhi, g_xlo, wh, wl, m0, n0, 0, t);
    CP_COMMIT();

    for (int it = 0; it < 32; it++) {
        if (it + 1 < 32) {
            gemm_issue(sb + ((it + 1) & 1) * G_BUF, g_xhi, g_xlo, wh, wl,
                       m0, n0, (it + 1) * 32, t);
            CP_COMMIT();
            CP_WAIT1();
        } else {
            CP_WAIT0();
        }
        __syncthreads();

        const uint32_t B = sb + (it & 1) * G_BUF;
        #pragma unroll
        for (int ks = 0; ks < 2; ks++) {
            const int k = 16 * ks;
            uint32_t aH[4][4], aL[4][4];
            #pragma unroll
            for (int mi = 0; mi < 4; mi++) {
                uint32_t aa = B + G_AH + ((64 * wm + 16 * mi + (l & 15)) * ASTR
                            + k + ((l >> 4) << 3)) * 2;
                ldmx4(aH[mi], aa);
                ldmx4(aL[mi], aa + (G_AL - G_AH));
            }
            #pragma unroll
            for (int nj = 0; nj < 2; nj++) {
                uint32_t wa = B + G_WH + ((k + (l & 7) + (((l >> 3) & 1) << 3)) * WSTR
                            + 32 * wn + 16 * nj + ((l >> 4) << 3)) * 2;
                uint32_t bH[4], bL[4];
                ldmx4t(bH, wa);
                ldmx4t(bL, wa + (G_WL - G_WH));
                #pragma unroll
                for (int mi = 0; mi < 4; mi++) {
                    mma_bf16(acc[mi][2 * nj],     aH[mi], bH);
                    mma_bf16(acc[mi][2 * nj + 1], aH[mi], bH + 2);
                    mma_bf16(acc[mi][2 * nj],     aH[mi], bL);
                    mma_bf16(acc[mi][2 * nj + 1], aH[mi], bL + 2);
                    mma_bf16(acc[mi][2 * nj],     aL[mi], bH);
                    mma_bf16(acc[mi][2 * nj + 1], aL[mi], bH + 2);
                }
            }
        }
        __syncthreads();
    }

    #pragma unroll
    for (int mi = 0; mi < 4; mi++) {
        #pragma unroll
        for (int ni = 0; ni < 4; ni++) {
            int col = n0 + 32 * wn + 8 * ni + 2 * lt;
            size_t r0 = (size_t)(m0 + 64 * wm + 16 * mi + lg) * NH + col;
            size_t r1 = r0 + 8 * NH;
            uint32_t hw, lw;
            split2(acc[mi][ni][0], acc[mi][ni][1], hw, lw);
            *(uint32_t*)&ohi[r0] = hw;
            *(uint32_t*)&olo[r0] = lw;
            split2(acc[mi][ni][2], acc[mi][ni][3], hw, lw);
            *(uint32_t*)&ohi[r1] = hw;
            *(uint32_t*)&olo[r1] = lw;
        }
    }
}

// ---------------------------------------------------------------------------
// Kernel 2: flash attention, 512 threads = 16 warps, warp grid 4(row)x4(quarter).
// TQ=64, TS=32. Warp (wr,wq): S tile 16 rows x 8 keys (n8 mma), O quarter
// 16 rows x 64 cols. 4 warps per SMSP for latency hiding.
// ---------------------------------------------------------------------------
#define QSTR 264
#define QROW_B (QSTR * 2)        // 528
#define TSA 32
#define PSTRB 80                 // P row stride bytes (40 bf16)

#define A_QHI 0
#define A_QLO (64 * QROW_B)                  // 33792
#define A_BUF0 (2 * 64 * QROW_B)             // 67584
#define T_KH 0
#define T_KL (TSA * QROW_B)                  // 16896
#define T_VH (2 * TSA * QROW_B)              // 33792
#define T_VL (3 * TSA * QROW_B)              // 50688
#define A_BUFSZ (4 * TSA * QROW_B)           // 67584
#define A_PHI (A_BUF0 + 2 * A_BUFSZ)         // 202752
#define A_RED (A_PHI + 64 * PSTRB)           // 207872
#define ATTN_SMEM (A_RED + 2048)             // 209920

__device__ __forceinline__ void attn_issue(uint32_t sbuf,
    const __nv_bfloat16* kh, const __nv_bfloat16* kl,
    const __nv_bfloat16* vh, const __nv_bfloat16* vl, int s0, int t)
{
    #pragma unroll
    for (int i = 0; i < 2; i++) {
        int idx = t + i * 512;
        int row = idx >> 5, seg = idx & 31;    // 32 rows x 32 segs
        uint32_t d = sbuf + row * QROW_B + seg * 16;
        size_t   g = (size_t)(s0 + row) * NH + seg * 8;
        cpa16(d + T_KH, kh + g);
        cpa16(d + T_KL, kl + g);
        cpa16(d + T_VH, vh + g);
        cpa16(d + T_VL, vl + g);
    }
}

__global__ void __launch_bounds__(512, 1)
attn_mma_kernel(float* __restrict__ out)
{
    extern __shared__ char smp[];
    const uint32_t sb = smem_u32(smp);
    float* redm = (float*)(smp + A_RED);           // [4][64] row max quarters
    float* reds = (float*)(smp + A_RED + 1024);    // [4][64] row sum quarters

    const int t   = threadIdx.x;
    const int wid = t >> 5;
    const int l   = t & 31;
    const int lg  = l >> 2;
    const int lt  = l & 3;
    const int wr  = wid & 3;          // row group: rows 16wr..16wr+15
    const int wq  = wid >> 2;         // quarter: S keys 8wq.., O cols 64wq..
    const int b   = blockIdx.y;
    const int q0  = ((NT / 64 - 1) - blockIdx.x) * 64;   // heavy tiles first

    // Q tile (hi+lo) -> smem
    {
        const __nv_bfloat16* qh = g_qhi + ((size_t)b * NT + q0) * NH;
        const __nv_bfloat16* ql = g_qlo + ((size_t)b * NT + q0) * NH;
        #pragma unroll
        for (int i = 0; i < 4; i++) {
            int idx = t + i * 512;
            int row = idx >> 5, seg = idx & 31;
            size_t g = (size_t)row * NH + seg * 8;
            *(uint4*)(smp + A_QHI + row * QROW_B + seg * 16) = *(const uint4*)(qh + g);
            *(uint4*)(smp + A_QLO + row * QROW_B + seg * 16) = *(const uint4*)(ql + g);
        }
    }

    const __nv_bfloat16* kh = g_khi + (size_t)b * NT * NH;
    const __nv_bfloat16* kl = g_klo + (size_t)b * NT * NH;
    const __nv_bfloat16* vh = g_vhi + (size_t)b * NT * NH;
    const __nv_bfloat16* vl = g_vlo + (size_t)b * NT * NH;

    float oacc[8][4];                 // O quarter: 16 rows x 64 cols
    #pragma unroll
    for (int i = 0; i < 8; i++)
        #pragma unroll
        for (int j = 0; j < 4; j++) oacc[i][j] = 0.f;

    float m0v = -3.0e38f, m1v = -3.0e38f, l0v = 0.f, l1v = 0.f;
    const int r0l = 16 * wr + lg;     // local rows
    const int r1l = r0l + 8;
    const int r0g = q0 + r0l;
    const int r1g = q0 + r1l;

    const int ntiles = q0 / TSA + 2;

    attn_issue(sb + A_BUF0, kh, kl, vh, vl, 0, t);
    CP_COMMIT();

    for (int it = 0; it < ntiles; it++) {
        const int s0 = it * TSA;
        CP_WAIT0();
        __syncthreads();                               // sync A: tile visible
        const uint32_t B = sb + A_BUF0 + (it & 1) * A_BUFSZ;

        // ---- S quarter = Qhi*Khi + Qhi*Klo + Qlo*Khi (16 rows x 8 keys)
        // Triple accumulators: 3 independent HMMA chains
        float sH[4], sX[4], sY[4];
        #pragma unroll
        for (int j = 0; j < 4; j++) { sH[j] = 0.f; sX[j] = 0.f; sY[j] = 0.f; }

        #pragma unroll 4
        for (int kk = 0; kk < 16; kk++) {
            const int k = kk * 16;
            uint32_t aH[4], aL[4];
            uint32_t qa = sb + A_QHI + (16 * wr + (l & 15)) * QROW_B
                        + (k + ((l >> 4) << 3)) * 2;
            ldmx4(aH, qa);
            ldmx4(aL, qa + (A_QLO - A_QHI));
            // K b-frag (8 keys x 16 k): two 8x8 matrices along k
            uint32_t ka = B + T_KH
                        + (8 * wq + (l & 7)) * QROW_B
                        + (k + ((l >> 3) & 1) * 8) * 2;
            uint32_t bH[2], bL[2];
            ldmx2(bH, ka);
            ldmx2(bL, ka + (T_KL - T_KH));
            mma_bf16(sH, aH, bH);
            mma_bf16(sX, aH, bL);
            mma_bf16(sY, aL, bH);
        }

        float sacc[4];
        #pragma unroll
        for (int j = 0; j < 4; j++) sacc[j] = sH[j] + sX[j] + sY[j];

        // ---- causal mask
        {
            int c = s0 + 8 * wq + 2 * lt;
            if (c     > r0g) sacc[0] = -3.0e38f;
            if (c + 1 > r0g) sacc[1] = -3.0e38f;
            if (c     > r1g) sacc[2] = -3.0e38f;
            if (c + 1 > r1g) sacc[3] = -3.0e38f;
        }

        // ---- quarter row max (quad shuffle), exchange across quarters
        float mx0 = fmaxf(sacc[0], sacc[1]);
        float mx1 = fmaxf(sacc[2], sacc[3]);
        mx0 = fmaxf(mx0, __shfl_xor_sync(0xffffffff, mx0, 1));
        mx0 = fmaxf(mx0, __shfl_xor_sync(0xffffffff, mx0, 2));
        mx1 = fmaxf(mx1, __shfl_xor_sync(0xffffffff, mx1, 1));
        mx1 = fmaxf(mx1, __shfl_xor_sync(0xffffffff, mx1, 2));
        if (lt == 0) {
            redm[wq * 64 + r0l] = mx0;
            redm[wq * 64 + r1l] = mx1;
        }
        __syncthreads();                               // sync B: maxes visible
        float mn0 = fmaxf(fmaxf(m0v, fmaxf(redm[r0l], redm[64 + r0l])),
                          fmaxf(redm[128 + r0l], redm[192 + r0l]));
        float mn1 = fmaxf(fmaxf(m1v, fmaxf(redm[r1l], redm[64 + r1l])),
                          fmaxf(redm[128 + r1l], redm[192 + r1l]));
        float al0 = __expf(m0v - mn0);
        float al1 = __expf(m1v - mn1);
        m0v = mn0; m1v = mn1;

        // ---- P = exp(S - m) -> smem (bf16 hi only); l from ROUNDED p
        {
            float e0 = __expf(sacc[0] - mn0);
            float e1 = __expf(sacc[1] - mn0);
            float e2 = __expf(sacc[2] - mn1);
            float e3 = __expf(sacc[3] - mn1);
            __nv_bfloat16 h0 = __float2bfloat16(e0);
            __nv_bfloat16 h1 = __float2bfloat16(e1);
            __nv_bfloat16 h2 = __float2bfloat16(e2);
            __nv_bfloat16 h3 = __float2bfloat16(e3);
            float ps0 = __bfloat162float(h0) + __bfloat162float(h1);
            float ps1 = __bfloat162float(h2) + __bfloat162float(h3);
            int cb = (8 * wq + 2 * lt) * 2;            // byte col offset
            *(uint32_t*)(smp + A_PHI + r0l * PSTRB + cb) = packbb(h0, h1);
            *(uint32_t*)(smp + A_PHI + r1l * PSTRB + cb) = packbb(h2, h3);
            ps0 += __shfl_xor_sync(0xffffffff, ps0, 1);
            ps0 += __shfl_xor_sync(0xffffffff, ps0, 2);
            ps1 += __shfl_xor_sync(0xffffffff, ps1, 1);
            ps1 += __shfl_xor_sync(0xffffffff, ps1, 2);
            if (lt == 0) {
                reds[wq * 64 + r0l] = ps0;
                reds[wq * 64 + r1l] = ps1;
            }
        }
        __syncthreads();                               // sync C: P + sums visible
        l0v = l0v * al0 + reds[r0l] + reds[64 + r0l]
                        + reds[128 + r0l] + reds[192 + r0l];
        l1v = l1v * al1 + reds[r1l] + reds[64 + r1l]
                        + reds[128 + r1l] + reds[192 + r1l];

        // ---- O rescale
        #pragma unroll
        for (int nb = 0; nb < 8; nb++) {
            oacc[nb][0] *= al0; oacc[nb][1] *= al0;
            oacc[nb][2] *= al1; oacc[nb][3] *= al1;
        }

        // ---- prefetch next tile (all warps past previous tile: safe)
        if (it + 1 < ntiles) {
            attn_issue(sb + A_BUF0 + ((it + 1) & 1) * A_BUFSZ, kh, kl, vh, vl,
                       (it + 1) * TSA, t);
            CP_COMMIT();
        }

        // ---- PV: O += Phi*Vhi + Phi*Vlo (16 rows x 64 cols)
        #pragma unroll
        for (int ks = 0; ks < 2; ks++) {
            uint32_t aH[4];
            uint32_t pa = sb + A_PHI + (16 * wr + (l & 15)) * PSTRB
                        + (16 * ks + ((l >> 4) << 3)) * 2;
            ldmx4(aH, pa);
            #pragma unroll
            for (int hb = 0; hb < 4; hb++) {
                uint32_t va = B + T_VH
                            + (16 * ks + (l & 7) + (((l >> 3) & 1) << 3)) * QROW_B
                            + (64 * wq + 16 * hb + ((l >> 4) << 3)) * 2;
                uint32_t bH[4], bL[4];
                ldmx4t(bH, va);
                ldmx4t(bL, va + (T_VL - T_VH));
                mma_bf16(oacc[2 * hb],     aH, bH);
                mma_bf16(oacc[2 * hb + 1], aH, bH + 2);
                mma_bf16(oacc[2 * hb],     aH, bL);
                mma_bf16(oacc[2 * hb + 1], aH, bL + 2);
            }
        }
    }

    // ---- epilogue: out = O / l
    {
        float inv0 = 1.0f / l0v;
        float inv1 = 1.0f / l1v;
        float* o0 = out + ((size_t)b * NT + r0g) * NH;
        float* o1 = out + ((size_t)b * NT + r1g) * NH;
        #pragma unroll
        for (int nb = 0; nb < 8; nb++) {
            int col = 64 * wq + 8 * nb + 2 * lt;
            *(float2*)&o0[col] = make_float2(oacc[nb][0] * inv0, oacc[nb][1] * inv0);
            *(float2*)&o1[col] = make_float2(oacc[nb][2] * inv1, oacc[nb][3] * inv1);
        }
    }
}

// ---------------------------------------------------------------------------
extern "C" void kernel_launch(void* const* d_in, const int* in_sizes, int n_in,
                              void* d_out, int out_size)
{
    const float* x  = (const float*)d_in[0];
    const float* Wq = (const float*)d_in[1];
    const float* Wk = (const float*)d_in[2];
    const float* Wv = (const float*)d_in[3];
    float* out = (float*)d_out;

    cudaFuncSetAttribute(qkv_gemm_kernel,
                         cudaFuncAttributeMaxDynamicSharedMemorySize, GEMM_SMEM);
    cudaFuncSetAttribute(attn_mma_kernel,
                         cudaFuncAttributeMaxDynamicSharedMemorySize, ATTN_SMEM);

    convert_x_kernel<<<16384, 256>>>(x);
    convert_w_kernel<<<768, 256>>>(Wq, Wk, Wv);
    qkv_gemm_kernel<<<dim3(2, (NB * NT) / 128, 3), 256, GEMM_SMEM>>>();
    attn_mma_kernel<<<dim3(NT / 64, NB), 512, ATTN_SMEM>>>(out);
}

// round 16
// speedup vs baseline: 1.1207x; 1.1207x over previous
#include <cuda_runtime.h>
#include <cuda_bf16.h>
#include <cstdint>

// Problem constants
#define NB 8
#define NT 2048
#define NC 1024
#define NH 256

// Scratch (device globals)
__device__ __nv_bfloat16 g_qhi[NB*NT*NH], g_qlo[NB*NT*NH];
__device__ __nv_bfloat16 g_khi[NB*NT*NH], g_klo[NB*NT*NH];
__device__ __nv_bfloat16 g_vhi[NB*NT*NH], g_vlo[NB*NT*NH];
__device__ __nv_bfloat16 g_xhi[NB*NT*NC], g_xlo[NB*NT*NC];
__device__ __nv_bfloat16 g_whi[3*NC*NH],  g_wlo[3*NC*NH];

__device__ __forceinline__ uint32_t smem_u32(const void* p) {
    uint32_t a;
    asm("{ .reg .u64 t; cvta.to.shared.u64 t, %1; cvt.u32.u64 %0, t; }"
        : "=r"(a) : "l"(p));
    return a;
}
__device__ __forceinline__ void ldmx4(uint32_t* r, uint32_t addr) {
    asm volatile("ldmatrix.sync.aligned.m8n8.x4.shared.b16 {%0,%1,%2,%3}, [%4];"
        : "=r"(r[0]), "=r"(r[1]), "=r"(r[2]), "=r"(r[3]) : "r"(addr));
}
__device__ __forceinline__ void ldmx4t(uint32_t* r, uint32_t addr) {
    asm volatile("ldmatrix.sync.aligned.m8n8.x4.trans.shared.b16 {%0,%1,%2,%3}, [%4];"
        : "=r"(r[0]), "=r"(r[1]), "=r"(r[2]), "=r"(r[3]) : "r"(addr));
}
__device__ __forceinline__ void mma_bf16(float* c, const uint32_t* a, const uint32_t* b) {
    asm volatile("mma.sync.aligned.m16n8k16.row.col.f32.bf16.bf16.f32 "
        "{%0,%1,%2,%3}, {%4,%5,%6,%7}, {%8,%9}, {%0,%1,%2,%3};"
        : "+f"(c[0]), "+f"(c[1]), "+f"(c[2]), "+f"(c[3])
        : "r"(a[0]), "r"(a[1]), "r"(a[2]), "r"(a[3]), "r"(b[0]), "r"(b[1]));
}
__device__ __forceinline__ void cpa16(uint32_t dst, const void* src) {
    asm volatile("cp.async.cg.shared.global [%0], [%1], 16;" :: "r"(dst), "l"(src));
}
#define CP_COMMIT() asm volatile("cp.async.commit_group;" ::: "memory")
#define CP_WAIT1()  asm volatile("cp.async.wait_group 1;" ::: "memory")
#define CP_WAIT0()  asm volatile("cp.async.wait_group 0;" ::: "memory")

__device__ __forceinline__ uint32_t packbb(__nv_bfloat16 a, __nv_bfloat16 b) {
    unsigned short ua = *reinterpret_cast<unsigned short*>(&a);
    unsigned short ub = *reinterpret_cast<unsigned short*>(&b);
    return (uint32_t)ua | ((uint32_t)ub << 16);
}
__device__ __forceinline__ void split2(float v0, float v1, uint32_t& hw, uint32_t& lw) {
    __nv_bfloat16 h0 = __float2bfloat16(v0);
    __nv_bfloat16 h1 = __float2bfloat16(v1);
    __nv_bfloat16 l0 = __float2bfloat16(v0 - __bfloat162float(h0));
    __nv_bfloat16 l1 = __float2bfloat16(v1 - __bfloat162float(h1));
    hw = packbb(h0, h1);
    lw = packbb(l0, l1);
}

// ---------------------------------------------------------------------------
// Prep kernels: fp32 -> split bf16 hi/lo
// ---------------------------------------------------------------------------
__global__ void __launch_bounds__(256)
convert_x_kernel(const float* __restrict__ x)
{
    int idx = blockIdx.x * 256 + threadIdx.x;
    float4 v = ((const float4*)x)[idx];
    uint32_t h01, l01, h23, l23;
    split2(v.x, v.y, h01, l01);
    split2(v.z, v.w, h23, l23);
    ((uint2*)g_xhi)[idx] = make_uint2(h01, h23);
    ((uint2*)g_xlo)[idx] = make_uint2(l01, l23);
}

__global__ void __launch_bounds__(256)
convert_w_kernel(const float* __restrict__ Wq, const float* __restrict__ Wk,
                 const float* __restrict__ Wv)
{
    int idx = blockIdx.x * 256 + threadIdx.x;
    int z = idx >> 16;
    int j = idx & 65535;
    const float* W = (z == 0) ? Wq : ((z == 1) ? Wk : Wv);
    float s = (z == 0) ? 16.0f : 1.0f;           // fold sqrt(H) into Wq
    float4 v = ((const float4*)W)[j];
    uint32_t h01, l01, h23, l23;
    split2(v.x * s, v.y * s, h01, l01);
    split2(v.z * s, v.w * s, h23, l23);
    ((uint2*)g_whi)[idx] = make_uint2(h01, h23);
    ((uint2*)g_wlo)[idx] = make_uint2(l01, l23);
}

// ---------------------------------------------------------------------------
// Kernel 1: QKV projection GEMM (unchanged from R10 — measured good)
// ---------------------------------------------------------------------------
#define ASTR 40
#define WSTR 136
#define G_AH  0
#define G_AL  10240
#define G_WH  20480
#define G_WL  29184
#define G_BUF 37888
#define GEMM_SMEM (2 * G_BUF)

__device__ __forceinline__ void gemm_issue(uint32_t sbuf, const __nv_bfloat16* xh,
                                           const __nv_bfloat16* xl,
                                           const __nv_bfloat16* wh,
                                           const __nv_bfloat16* wl,
                                           int m0, int n0, int k0, int t)
{
    #pragma unroll
    for (int i = 0; i < 2; i++) {
        int idx = t + 256 * i;
        {
            int row = idx >> 2, seg = idx & 3;
            uint32_t d = sbuf + G_AH + row * (ASTR * 2) + seg * 16;
            size_t   g = (size_t)(m0 + row) * NC + k0 + seg * 8;
            cpa16(d, xh + g);
            cpa16(d + (G_AL - G_AH), xl + g);
        }
        {
            int row = idx >> 4, seg = idx & 15;
            uint32_t d = sbuf + G_WH + row * (WSTR * 2) + seg * 16;
            size_t   g = (size_t)(k0 + row) * NH + n0 + seg * 8;
            cpa16(d, wh + g);
            cpa16(d + (G_WL - G_WH), wl + g);
        }
    }
}

__global__ void __launch_bounds__(256, 2)
qkv_gemm_kernel()
{
    extern __shared__ char smg[];
    const uint32_t sb = smem_u32(smg);

    const int z = blockIdx.z;
    const __nv_bfloat16* wh = g_whi + (size_t)z * NC * NH;
    const __nv_bfloat16* wl = g_wlo + (size_t)z * NC * NH;
    __nv_bfloat16* ohi = (z == 0) ? g_qhi : ((z == 1) ? g_khi : g_vhi);
    __nv_bfloat16* olo = (z == 0) ? g_qlo : ((z == 1) ? g_klo : g_vlo);

    const int m0 = blockIdx.y * 128;
    const int n0 = blockIdx.x * 128;
    const int t  = threadIdx.x;
    const int l  = t & 31;
    const int wid = t >> 5;
    const int wm = wid & 1;
    const int wn = wid >> 1;
    const int lg = l >> 2;
    const int lt = l & 3;

    float acc[4][4][4];
    #pragma unroll
    for (int i = 0; i < 4; i++)
        #pragma unroll
        for (int j = 0; j < 4; j++)
            #pragma unroll
            for (int k = 0; k < 4; k++) acc[i][j][k] = 0.f;

    gemm_issue(sb, g_xhi, g_xlo, wh, wl, m0, n0, 0, t);
    CP_COMMIT();

    for (int it = 0; it < 32; it++) {
        if (it + 1 < 32) {
            gemm_issue(sb + ((it + 1) & 1) * G_BUF, g_xhi, g_xlo, wh, wl,
                       m0, n0, (it + 1) * 32, t);
            CP_COMMIT();
            CP_WAIT1();
        } else {
            CP_WAIT0();
        }
        __syncthreads();

        const uint32_t B = sb + (it & 1) * G_BUF;
        #pragma unroll
        for (int ks = 0; ks < 2; ks++) {
            const int k = 16 * ks;
            uint32_t aH[4][4], aL[4][4];
            #pragma unroll
            for (int mi = 0; mi < 4; mi++) {
                uint32_t aa = B + G_AH + ((64 * wm + 16 * mi + (l & 15)) * ASTR
                            + k + ((l >> 4) << 3)) * 2;
                ldmx4(aH[mi], aa);
                ldmx4(aL[mi], aa + (G_AL - G_AH));
            }
            #pragma unroll
            for (int nj = 0; nj < 2; nj++) {
                uint32_t wa = B + G_WH + ((k + (l & 7) + (((l >> 3) & 1) << 3)) * WSTR
                            + 32 * wn + 16 * nj + ((l >> 4) << 3)) * 2;
                uint32_t bH[4], bL[4];
                ldmx4t(bH, wa);
                ldmx4t(bL, wa + (G_WL - G_WH));
                #pragma unroll
                for (int mi = 0; mi < 4; mi++) {
                    mma_bf16(acc[mi][2 * nj],     aH[mi], bH);
                    mma_bf16(acc[mi][2 * nj + 1], aH[mi], bH + 2);
                    mma_bf16(acc[mi][2 * nj],     aH[mi], bL);
                    mma_bf16(acc[mi][2 * nj + 1], aH[mi], bL + 2);
                    mma_bf16(acc[mi][2 * nj],     aL[mi], bH);
                    mma_bf16(acc[mi][2 * nj + 1], aL[mi], bH + 2);
                }
            }
        }
        __syncthreads();
    }

    #pragma unroll
    for (int mi = 0; mi < 4; mi++) {
        #pragma unroll
        for (int ni = 0; ni < 4; ni++) {
            int col = n0 + 32 * wn + 8 * ni + 2 * lt;
            size_t r0 = (size_t)(m0 + 64 * wm + 16 * mi + lg) * NH + col;
            size_t r1 = r0 + 8 * NH;
            uint32_t hw, lw;
            split2(acc[mi][ni][0], acc[mi][ni][1], hw, lw);
            *(uint32_t*)&ohi[r0] = hw;
            *(uint32_t*)&olo[r0] = lw;
            split2(acc[mi][ni][2], acc[mi][ni][3], hw, lw);
            *(uint32_t*)&ohi[r1] = hw;
            *(uint32_t*)&olo[r1] = lw;
        }
    }
}

// ---------------------------------------------------------------------------
// Kernel 2: flash attention. TQ=32 (512 CTAs), TS=64 double-tiles.
// 256 threads = 8 warps, grid 2(row)x4(key/O-quarter).
// Warp: S 16 rows x 16 keys, PV 16 rows x 64 O-cols (oacc = 32 floats).
// Single K buf + single V buf, commit-group pipeline (K prefetched 1 tile
// ahead after the max barrier; V load hidden behind S compute).
// ---------------------------------------------------------------------------
#define QSTR 264
#define QROW_B (QSTR * 2)        // 528
#define TSA 64
#define PSTRB 144                // P row stride bytes (72 bf16)

#define A_QHI 0
#define A_QLO (32 * QROW_B)                  // 16896
#define A_KH  (2 * 32 * QROW_B)              // 33792
#define A_KL  (A_KH + 64 * QROW_B)           // 67584
#define A_VH  (A_KH + 2 * 64 * QROW_B)       // 101376
#define A_VL  (A_VH + 64 * QROW_B)           // 135168
#define A_PHI (A_VH + 2 * 64 * QROW_B)       // 168960
#define A_RED (A_PHI + 32 * PSTRB)           // 173568
#define ATTN_SMEM (A_RED + 1024)             // 174592

// load a 64-row (hi+lo) K or V tile: 16 cp.async per thread
__device__ __forceinline__ void attn_issue_kv(char* smp, int offh, int offl,
    const __nv_bfloat16* gh, const __nv_bfloat16* gl, int s0, int t)
{
    const uint32_t sb = smem_u32(smp);
    #pragma unroll
    for (int i = 0; i < 8; i++) {
        int idx = t + i * 256;
        int row = idx >> 5, seg = idx & 31;    // 64 rows x 32 segs
        uint32_t d = sb + row * QROW_B + seg * 16;
        size_t   g = (size_t)(s0 + row) * NH + seg * 8;
        cpa16(d + offh, gh + g);
        cpa16(d + offl, gl + g);
    }
}

__global__ void __launch_bounds__(256, 1)
attn_mma_kernel(float* __restrict__ out)
{
    extern __shared__ char smp[];
    const uint32_t sb = smem_u32(smp);
    float* redm = (float*)(smp + A_RED);          // [4][32] row max quarters
    float* reds = (float*)(smp + A_RED + 512);    // [4][32] row sum quarters

    const int t   = threadIdx.x;
    const int wid = t >> 5;
    const int l   = t & 31;
    const int lg  = l >> 2;
    const int lt  = l & 3;
    const int wr  = wid & 1;          // row group: rows 16wr..16wr+15
    const int wc  = wid >> 1;         // quarter: S keys 16wc.., O cols 64wc..
    const int b   = blockIdx.y;
    const int qi  = (NT / 32 - 1) - blockIdx.x;          // heavy tiles first
    const int q0  = qi * 32;

    // Q tile (hi+lo) -> smem (32 rows)
    {
        const __nv_bfloat16* qh = g_qhi + ((size_t)b * NT + q0) * NH;
        const __nv_bfloat16* ql = g_qlo + ((size_t)b * NT + q0) * NH;
        #pragma unroll
        for (int i = 0; i < 4; i++) {
            int idx = t + i * 256;
            int row = idx >> 5, seg = idx & 31;
            size_t g = (size_t)row * NH + seg * 8;
            *(uint4*)(smp + A_QHI + row * QROW_B + seg * 16) = *(const uint4*)(qh + g);
            *(uint4*)(smp + A_QLO + row * QROW_B + seg * 16) = *(const uint4*)(ql + g);
        }
    }

    const __nv_bfloat16* kh = g_khi + (size_t)b * NT * NH;
    const __nv_bfloat16* kl = g_klo + (size_t)b * NT * NH;
    const __nv_bfloat16* vh = g_vhi + (size_t)b * NT * NH;
    const __nv_bfloat16* vl = g_vlo + (size_t)b * NT * NH;

    float oacc[8][4];                 // O quarter: 16 rows x 64 cols
    #pragma unroll
    for (int i = 0; i < 8; i++)
        #pragma unroll
        for (int j = 0; j < 4; j++) oacc[i][j] = 0.f;

    float m0v = -3.0e38f, m1v = -3.0e38f, l0v = 0.f, l1v = 0.f;
    const int r0l = 16 * wr + lg;     // local rows (0..31)
    const int r1l = r0l + 8;
    const int r0g = q0 + r0l;
    const int r1g = q0 + r1l;

    const int ntiles = qi / 2 + 1;    // keys 0 .. 64*ntiles-1 >= q0+31

    attn_issue_kv(smp, A_KH, A_KL, kh, kl, 0, t);   // K_0
    CP_COMMIT();

    for (int it = 0; it < ntiles; it++) {
        const int s0 = it * TSA;
        attn_issue_kv(smp, A_VH, A_VL, vh, vl, s0, t);   // V_it
        CP_COMMIT();
        CP_WAIT1();                                  // K_it done (V pending)
        __syncthreads();                             // sync A: K visible

        // ---- S quarter = Qhi*Khi + Qhi*Klo + Qlo*Khi (16 rows x 16 keys)
        float sH[2][4], sX[2][4], sY[2][4];
        #pragma unroll
        for (int i = 0; i < 2; i++)
            #pragma unroll
            for (int j = 0; j < 4; j++) { sH[i][j] = 0.f; sX[i][j] = 0.f; sY[i][j] = 0.f; }

        #pragma unroll 4
        for (int kk = 0; kk < 16; kk++) {
            const int k = kk * 16;
            uint32_t aH[4], aL[4];
            uint32_t qa = sb + A_QHI + (16 * wr + (l & 15)) * QROW_B
                        + (k + ((l >> 4) << 3)) * 2;
            ldmx4(aH, qa);
            ldmx4(aL, qa + (A_QLO - A_QHI));
            uint32_t ka = sb + A_KH
                        + (16 * wc + (l & 7) + ((l >> 4) << 3)) * QROW_B
                        + (k + (((l >> 3) & 1) << 3)) * 2;
            uint32_t bH[4], bL[4];
            ldmx4(bH, ka);
            ldmx4(bL, ka + (A_KL - A_KH));
            mma_bf16(sH[0], aH, bH);
            mma_bf16(sH[1], aH, bH + 2);
            mma_bf16(sX[0], aH, bL);
            mma_bf16(sX[1], aH, bL + 2);
            mma_bf16(sY[0], aL, bH);
            mma_bf16(sY[1], aL, bH + 2);
        }

        float sacc[2][4];
        #pragma unroll
        for (int i = 0; i < 2; i++)
            #pragma unroll
            for (int j = 0; j < 4; j++)
                sacc[i][j] = sH[i][j] + sX[i][j] + sY[i][j];

        // ---- causal mask
        #pragma unroll
        for (int nb = 0; nb < 2; nb++) {
            int c = s0 + 16 * wc + 8 * nb + 2 * lt;
            if (c     > r0g) sacc[nb][0] = -3.0e38f;
            if (c + 1 > r0g) sacc[nb][1] = -3.0e38f;
            if (c     > r1g) sacc[nb][2] = -3.0e38f;
            if (c + 1 > r1g) sacc[nb][3] = -3.0e38f;
        }

        // ---- quarter row max (quad shuffle), exchange across quarters
        float mx0 = fmaxf(fmaxf(sacc[0][0], sacc[0][1]), fmaxf(sacc[1][0], sacc[1][1]));
        float mx1 = fmaxf(fmaxf(sacc[0][2], sacc[0][3]), fmaxf(sacc[1][2], sacc[1][3]));
        mx0 = fmaxf(mx0, __shfl_xor_sync(0xffffffff, mx0, 1));
        mx0 = fmaxf(mx0, __shfl_xor_sync(0xffffffff, mx0, 2));
        mx1 = fmaxf(mx1, __shfl_xor_sync(0xffffffff, mx1, 1));
        mx1 = fmaxf(mx1, __shfl_xor_sync(0xffffffff, mx1, 2));
        if (lt == 0) {
            redm[wc * 32 + r0l] = mx0;
            redm[wc * 32 + r1l] = mx1;
        }
        __syncthreads();                             // sync B: maxes visible
        float mn0 = fmaxf(fmaxf(m0v, fmaxf(redm[r0l], redm[32 + r0l])),
                          fmaxf(redm[64 + r0l], redm[96 + r0l]));
        float mn1 = fmaxf(fmaxf(m1v, fmaxf(redm[r1l], redm[32 + r1l])),
                          fmaxf(redm[64 + r1l], redm[96 + r1l]));
        float al0 = __expf(m0v - mn0);
        float al1 = __expf(m1v - mn1);
        m0v = mn0; m1v = mn1;

        // ---- prefetch K_{it+1} (K buffer free: all S reads done at sync B)
        if (it + 1 < ntiles) {
            attn_issue_kv(smp, A_KH, A_KL, kh, kl, (it + 1) * TSA, t);
            CP_COMMIT();
            CP_WAIT1();                              // V_it done (K_{it+1} pending)
        } else {
            CP_WAIT0();                              // V_it done
        }

        // ---- P = exp(S - m) -> smem (bf16 hi only); l from ROUNDED p
        float ps0 = 0.f, ps1 = 0.f;
        #pragma unroll
        for (int nb = 0; nb < 2; nb++) {
            float e0 = __expf(sacc[nb][0] - mn0);
            float e1 = __expf(sacc[nb][1] - mn0);
            float e2 = __expf(sacc[nb][2] - mn1);
            float e3 = __expf(sacc[nb][3] - mn1);
            __nv_bfloat16 h0 = __float2bfloat16(e0);
            __nv_bfloat16 h1 = __float2bfloat16(e1);
            __nv_bfloat16 h2 = __float2bfloat16(e2);
            __nv_bfloat16 h3 = __float2bfloat16(e3);
            ps0 += __bfloat162float(h0) + __bfloat162float(h1);
            ps1 += __bfloat162float(h2) + __bfloat162float(h3);
            int cb = (16 * wc + 8 * nb + 2 * lt) * 2;
            *(uint32_t*)(smp + A_PHI + r0l * PSTRB + cb) = packbb(h0, h1);
            *(uint32_t*)(smp + A_PHI + r1l * PSTRB + cb) = packbb(h2, h3);
        }
        ps0 += __shfl_xor_sync(0xffffffff, ps0, 1);
        ps0 += __shfl_xor_sync(0xffffffff, ps0, 2);
        ps1 += __shfl_xor_sync(0xffffffff, ps1, 1);
        ps1 += __shfl_xor_sync(0xffffffff, ps1, 2);
        if (lt == 0) {
            reds[wc * 32 + r0l] = ps0;
            reds[wc * 32 + r1l] = ps1;
        }
        __syncthreads();                             // sync C: P + V + sums visible
        l0v = l0v * al0 + reds[r0l] + reds[32 + r0l]
                        + reds[64 + r0l] + reds[96 + r0l];
        l1v = l1v * al1 + reds[r1l] + reds[32 + r1l]
                        + reds[64 + r1l] + reds[96 + r1l];

        // ---- O rescale
        #pragma unroll
        for (int nb = 0; nb < 8; nb++) {
            oacc[nb][0] *= al0; oacc[nb][1] *= al0;
            oacc[nb][2] *= al1; oacc[nb][3] *= al1;
        }

        // ---- PV: O += Phi*Vhi + Phi*Vlo (16 rows x 64 cols, K=64)
        #pragma unroll
        for (int ks = 0; ks < 4; ks++) {
            uint32_t aH[4];
            uint32_t pa = sb + A_PHI + (16 * wr + (l & 15)) * PSTRB
                        + (16 * ks + ((l >> 4) << 3)) * 2;
            ldmx4(aH, pa);
            #pragma unroll
            for (int hb = 0; hb < 4; hb++) {
                uint32_t va = sb + A_VH
                            + (16 * ks + (l & 7) + (((l >> 3) & 1) << 3)) * QROW_B
                            + (64 * wc + 16 * hb + ((l >> 4) << 3)) * 2;
                uint32_t bH[4], bL[4];
                ldmx4t(bH, va);
                ldmx4t(bL, va + (A_VL - A_VH));
                mma_bf16(oacc[2 * hb],     aH, bH);
                mma_bf16(oacc[2 * hb + 1], aH, bH + 2);
                mma_bf16(oacc[2 * hb],     aH, bL);
                mma_bf16(oacc[2 * hb + 1], aH, bL + 2);
            }
        }
        __syncthreads();                             // sync D: free V buf + P
    }

    // ---- epilogue: out = O / l
    {
        float inv0 = 1.0f / l0v;
        float inv1 = 1.0f / l1v;
        float* o0 = out + ((size_t)b * NT + r0g) * NH;
        float* o1 = out + ((size_t)b * NT + r1g) * NH;
        #pragma unroll
        for (int nb = 0; nb < 8; nb++) {
            int col = 64 * wc + 8 * nb + 2 * lt;
            *(float2*)&o0[col] = make_float2(oacc[nb][0] * inv0, oacc[nb][1] * inv0);
            *(float2*)&o1[col] = make_float2(oacc[nb][2] * inv1, oacc[nb][3] * inv1);
        }
    }
}

// ---------------------------------------------------------------------------
extern "C" void kernel_launch(void* const* d_in, const int* in_sizes, int n_in,
                              void* d_out, int out_size)
{
    const float* x  = (const float*)d_in[0];
    const float* Wq = (const float*)d_in[1];
    const float* Wk = (const float*)d_in[2];
    const float* Wv = (const float*)d_in[3];
    float* out = (float*)d_out;

    cudaFuncSetAttribute(qkv_gemm_kernel,
                         cudaFuncAttributeMaxDynamicSharedMemorySize, GEMM_SMEM);
    cudaFuncSetAttribute(attn_mma_kernel,
                         cudaFuncAttributeMaxDynamicSharedMemorySize, ATTN_SMEM);

    convert_x_kernel<<<16384, 256>>>(x);
    convert_w_kernel<<<768, 256>>>(Wq, Wk, Wv);
    qkv_gemm_kernel<<<dim3(2, (NB * NT) / 128, 3), 256, GEMM_SMEM>>>();
    attn_mma_kernel<<<dim3(NT / 32, NB), 256, ATTN_SMEM>>>(out);
}